// round 14
// baseline (speedup 1.0000x reference)
#include <cuda_runtime.h>
#include <math.h>

// Problem constants
#define B_TOT  16384
#define T_LEN  128
#define F_DIM  9
#define H_DIM  128
#define O_DIM  12
#define G_DIM  512     // 4*H
#define TILE_B 64
#define NTH    512     // 16 warps: warp owns 8 rows x 256 cols (2 units x 4 gates per lane)
#define KC     16      // k-chunk staged per ping-pong step

typedef unsigned long long ull;

// ---------------- packed f32x2 helpers ----------------
__device__ __forceinline__ ull pk2(float x, float y) {
    ull r;
    asm("mov.b64 %0, {%1, %2};" : "=l"(r) : "f"(x), "f"(y));
    return r;
}
__device__ __forceinline__ void unpk2(ull v, float& lo, float& hi) {
    asm("mov.b64 {%0, %1}, %2;" : "=f"(lo), "=f"(hi) : "l"(v));
}
__device__ __forceinline__ ull fma2(ull a, ull b, ull c) {
    ull d;
    asm("fma.rn.f32x2 %0, %1, %2, %3;" : "=l"(d) : "l"(a), "l"(b), "l"(c));
    return d;
}

// ---------------- pointwise gate math ----------------
__device__ __forceinline__ float sigf(float x) {
    return __fdividef(1.0f, 1.0f + __expf(-x));
}
__device__ __forceinline__ float tanhfast(float x) {
    float xc = fminf(fmaxf(x, -15.0f), 15.0f);
    float e = __expf(2.0f * xc);
    return __fdividef(e - 1.0f, e + 1.0f);
}

// ---------------- staging permutation ----------------
// Column c (0..511) of a gate matrix decomposes as: g = c>>7 (gate), hf = (c>>6)&1,
// l = (c>>1)&31 (lane), u = c&1. Staged position within a 512-float k-row:
//   pos = (g>>1)*256 + hf*128 + l*4 + (g&1)*2 + u
// Reader (warp-half hf, lane l) then finds its 8 weights per k as TWO contiguous
// float4s at offsets  sel*256 + hf*128 + l*4 , sel = 0/1  -> LDS.128 as ulonglong2,
// each ull already the packed f32x2 (unit u0, u0+1) for one gate.
__device__ __forceinline__ int stage_pos(int c) {
    int g = c >> 7, hf = (c >> 6) & 1, l = (c >> 1) & 31, u = c & 1;
    return ((g >> 1) << 8) + (hf << 7) + (l << 2) + ((g & 1) << 1) + u;
}

// ---------------- precomputed folded weights ----------------
// WxP = (Wih0 @ W_in) stored PERMUTED: WxP[f*512 + stage_pos(c)]
// beff = Wih0 @ b_in + bih0 + bhh0 ; bias1 = bih1 + bhh1
__device__ float g_WxP[F_DIM * G_DIM];
__device__ float g_beff[G_DIM];
__device__ float g_bias1[G_DIM];

__global__ void precompute_kernel(const float* __restrict__ Wih0,
                                  const float* __restrict__ W_in,
                                  const float* __restrict__ b_in,
                                  const float* __restrict__ bih0,
                                  const float* __restrict__ bhh0,
                                  const float* __restrict__ bih1,
                                  const float* __restrict__ bhh1) {
    int j = threadIdx.x;  // 0..511 : column of the gate matrices
    float acc[F_DIM];
#pragma unroll
    for (int f = 0; f < F_DIM; f++) acc[f] = 0.0f;
    float bacc = 0.0f;
    for (int k = 0; k < H_DIM; k++) {
        float w = Wih0[j * H_DIM + k];
        bacc += w * b_in[k];
#pragma unroll
        for (int f = 0; f < F_DIM; f++) acc[f] += w * W_in[k * F_DIM + f];
    }
    int pos = stage_pos(j);
#pragma unroll
    for (int f = 0; f < F_DIM; f++) g_WxP[f * G_DIM + pos] = acc[f];
    g_beff[j] = bacc + bih0[j] + bhh0[j];
    g_bias1[j] = bih1[j] + bhh1[j];
}

// ---------------- helpers for the main kernel ----------------
__device__ __forceinline__ void init_acc(const float* __restrict__ sBias, int u0,
                                         ull (&acc)[4][8]) {
#pragma unroll
    for (int g = 0; g < 4; g++) {
        ull b = *(const ull*)(sBias + g * H_DIM + u0);
#pragma unroll
        for (int r = 0; r < 8; r++) acc[g][r] = b;
    }
}

// prefetch one KC=16 chunk of one weight matrix: thread owns column j
__device__ __forceinline__ void ldg_chunk(int m,
                                          const float* __restrict__ Whh0,
                                          const float* __restrict__ Wih1,
                                          const float* __restrict__ Whh1,
                                          int j, float4 (&ra)[4]) {
    const float* src = (m < 8) ? Whh0 : ((m < 16) ? Wih1 : Whh1);
    const float4* p = (const float4*)(src + (size_t)j * H_DIM + (m & 7) * KC);
#pragma unroll
    for (int i = 0; i < 4; i++) ra[i] = p[i];
}

// store chunk into staging buffer in permuted layout: buf[k*512 + pos]
__device__ __forceinline__ void sts_chunk(float* __restrict__ buf, int pos,
                                          const float4 (&ra)[4]) {
#pragma unroll
    for (int i = 0; i < 4; i++) {
        buf[(i * 4 + 0) * G_DIM + pos] = ra[i].x;
        buf[(i * 4 + 1) * G_DIM + pos] = ra[i].y;
        buf[(i * 4 + 2) * G_DIM + pos] = ra[i].z;
        buf[(i * 4 + 3) * G_DIM + pos] = ra[i].w;
    }
}

// Inner GEMM over a KC=16 chunk. Sp -> S[r0][k0] (row stride 128).
// base = hf*128 + lane*4 : this thread's slot within a staged k-row.
__device__ __forceinline__ void gemm16(const float* __restrict__ Sp,
                                       const float* __restrict__ buf,
                                       int base, ull (&acc)[4][8]) {
#pragma unroll
    for (int g2 = 0; g2 < 8; g2++) {          // groups of 2 k
        float2 h2[8];
#pragma unroll
        for (int r = 0; r < 8; r++)
            h2[r] = *(const float2*)(Sp + r * H_DIM + g2 * 2);
#pragma unroll
        for (int kk = 0; kk < 2; kk++) {
            const float* wp = buf + (g2 * 2 + kk) * G_DIM + base;
            ulonglong2 wa = *(const ulonglong2*)(wp);         // gates i,f (2 units each)
            ulonglong2 wb = *(const ulonglong2*)(wp + 256);   // gates g,o
#pragma unroll
            for (int r = 0; r < 8; r++) {
                float hv = kk ? h2[r].y : h2[r].x;
                ull hp = pk2(hv, hv);
                acc[0][r] = fma2(wa.x, hp, acc[0][r]);
                acc[1][r] = fma2(wa.y, hp, acc[1][r]);
                acc[2][r] = fma2(wb.x, hp, acc[2][r]);
                acc[3][r] = fma2(wb.y, hp, acc[3][r]);
            }
        }
    }
}

// x-part GEMM: K=9, permuted weights straight from global (L1/L2 resident, 18KB)
__device__ __forceinline__ void gemm_x(const float* __restrict__ Sp,  // sXs + r0*12
                                       int base, ull (&acc)[4][8]) {
#pragma unroll
    for (int k = 0; k < F_DIM; k++) {
        const float* wp = g_WxP + k * G_DIM + base;
        ulonglong2 wa = *(const ulonglong2*)(wp);
        ulonglong2 wb = *(const ulonglong2*)(wp + 256);
#pragma unroll
        for (int r = 0; r < 8; r++) {
            float hv = Sp[r * 12 + k];
            ull hp = pk2(hv, hv);
            acc[0][r] = fma2(wa.x, hp, acc[0][r]);
            acc[1][r] = fma2(wa.y, hp, acc[1][r]);
            acc[2][r] = fma2(wb.x, hp, acc[2][r]);
            acc[3][r] = fma2(wb.y, hp, acc[3][r]);
        }
    }
}

__device__ __forceinline__ void cell_update(ull (&acc)[4][8],
                                            float* __restrict__ sC,
                                            float* __restrict__ sH,
                                            int r0, int u0) {
#pragma unroll
    for (int r = 0; r < 8; r++) {
        float i0, i1, f0, f1, gg0, gg1, o0, o1;
        unpk2(acc[0][r], i0, i1);
        unpk2(acc[1][r], f0, f1);
        unpk2(acc[2][r], gg0, gg1);
        unpk2(acc[3][r], o0, o1);
        float* cp = sC + (r0 + r) * H_DIM + u0;
        float2 c2 = *(float2*)cp;
        float cn0 = sigf(f0) * c2.x + sigf(i0) * tanhfast(gg0);
        float cn1 = sigf(f1) * c2.y + sigf(i1) * tanhfast(gg1);
        float hn0 = sigf(o0) * tanhfast(cn0);
        float hn1 = sigf(o1) * tanhfast(cn1);
        *(float2*)cp = make_float2(cn0, cn1);
        *(float2*)(sH + (r0 + r) * H_DIM + u0) = make_float2(hn0, hn1);
    }
}

// ---------------- main persistent-tile LSTM kernel ----------------
// grid = 256 CTAs x 512 threads; each CTA owns 64 batch rows for all 128 steps.
// Warp (w): hf = w>>3 (column half), row group rg = w&7 -> rows rg*8..rg*8+7.
// Lane owns units u0 = hf*64 + lane*2 (+1) for all 4 gates. acc = 32 ull.
__global__ void __launch_bounds__(NTH, 1)
lstm_main(const float* __restrict__ x,
          const float* __restrict__ Whh0,
          const float* __restrict__ Wih1,
          const float* __restrict__ Whh1,
          const float* __restrict__ W_out,
          const float* __restrict__ b_out,
          float* __restrict__ out) {
    extern __shared__ float smem[];
    float* sXs    = smem;                  // 64*12  = 768
    float* sH0    = sXs + 768;             // 8192
    float* sH1    = sH0 + 8192;            // 8192
    float* sC0    = sH1 + 8192;            // 8192
    float* sC1    = sC0 + 8192;            // 8192
    float* sW     = sC1 + 8192;            // 2 x 8192 ping-pong (permuted chunks)
    float* sBeff  = sW + 16384;            // 512
    float* sBias1 = sBeff + 512;           // 512

    const int tid  = threadIdx.x;
    const int lane = tid & 31;
    const int warp = tid >> 5;
    const int hf   = warp >> 3;
    const int r0   = (warp & 7) * 8;        // 8 rows per warp
    const int u0   = hf * 64 + lane * 2;    // 2 units per gate per thread
    const int base = hf * 128 + lane * 4;   // slot within staged k-row
    const int b0   = blockIdx.x * TILE_B;
    const int spos = stage_pos(tid);        // where this thread's loaded column lands

    // init states + resident biases
    for (int i = tid; i < 4 * 8192; i += NTH) sH0[i] = 0.0f;   // H0,H1,C0,C1 contiguous
    for (int i = tid; i < G_DIM; i += NTH) { sBeff[i] = g_beff[i]; sBias1[i] = g_bias1[i]; }
    __syncthreads();

    float4 ra[4];
    ldg_chunk(0, Whh0, Wih1, Whh1, tid, ra);   // prefetch chunk 0

    for (int t = 0; t < T_LEN; t++) {
        // x tile for this timestep
        for (int i = tid; i < TILE_B * F_DIM; i += NTH) {
            int r = i / F_DIM, f = i - r * F_DIM;
            sXs[r * 12 + f] = x[(size_t)(b0 + r) * (T_LEN * F_DIM) + t * F_DIM + f];
        }
        __syncthreads();

        // ---- layer 0 ----
        ull acc[4][8];
        init_acc(sBeff, u0, acc);
        gemm_x(&sXs[r0 * 12], base, acc);               // folded x-part, K=9
#pragma unroll 1
        for (int m = 0; m < 8; m++) {                   // Whh0, K=128
            float* buf = sW + (m & 1) * 8192;
            sts_chunk(buf, spos, ra);
            ldg_chunk(m + 1, Whh0, Wih1, Whh1, tid, ra);
            __syncthreads();
            gemm16(&sH0[r0 * H_DIM + m * KC], buf, base, acc);
        }
        __syncthreads();
        cell_update(acc, sC0, sH0, r0, u0);
        __syncthreads();

        // ---- layer 1 ----
        init_acc(sBias1, u0, acc);
#pragma unroll 1
        for (int m = 8; m < 24; m++) {                  // Wih1 (h0-new) then Whh1 (h1-old)
            float* buf = sW + (m & 1) * 8192;
            sts_chunk(buf, spos, ra);
            int mn = (m + 1 == 24) ? 0 : (m + 1);
            ldg_chunk(mn, Whh0, Wih1, Whh1, tid, ra);
            __syncthreads();
            const float* S = (m < 16) ? sH0 : sH1;
            gemm16(&S[r0 * H_DIM + (m & 7) * KC], buf, base, acc);
        }
        __syncthreads();
        cell_update(acc, sC1, sH1, r0, u0);
        __syncthreads();
    }

    // ---- epilogue: logits + softmax on last h1 ----
    if (tid < TILE_B) {
        int r = tid;
        const float* hr = &sH1[r * H_DIM];
        float lg[O_DIM];
#pragma unroll
        for (int o = 0; o < O_DIM; o++) {
            float s = b_out[o];
            for (int k = 0; k < H_DIM; k++) s += hr[k] * W_out[o * H_DIM + k];
            lg[o] = s;
        }
        float m = lg[0];
#pragma unroll
        for (int o = 1; o < O_DIM; o++) m = fmaxf(m, lg[o]);
        float sum = 0.0f;
#pragma unroll
        for (int o = 0; o < O_DIM; o++) { lg[o] = __expf(lg[o] - m); sum += lg[o]; }
        float inv = __fdividef(1.0f, sum);
#pragma unroll
        for (int o = 0; o < O_DIM; o++) out[(size_t)(b0 + r) * O_DIM + o] = lg[o] * inv;
    }
}

// ---------------- launch ----------------
extern "C" void kernel_launch(void* const* d_in, const int* in_sizes, int n_in,
                              void* d_out, int out_size) {
    (void)in_sizes; (void)n_in; (void)out_size;
    const float* x     = (const float*)d_in[0];
    const float* W_in  = (const float*)d_in[1];
    const float* b_in  = (const float*)d_in[2];
    const float* Wih0  = (const float*)d_in[3];
    const float* Whh0  = (const float*)d_in[4];
    const float* bih0  = (const float*)d_in[5];
    const float* bhh0  = (const float*)d_in[6];
    const float* Wih1  = (const float*)d_in[7];
    const float* Whh1  = (const float*)d_in[8];
    const float* bih1  = (const float*)d_in[9];
    const float* bhh1  = (const float*)d_in[10];
    const float* W_out = (const float*)d_in[11];
    const float* b_out = (const float*)d_in[12];
    float* out = (float*)d_out;

    const size_t smem_bytes = (size_t)(768 + 8192 * 6 + 1024) * sizeof(float); // 203776
    cudaFuncSetAttribute(lstm_main, cudaFuncAttributeMaxDynamicSharedMemorySize, (int)smem_bytes);

    precompute_kernel<<<1, G_DIM>>>(Wih0, W_in, b_in, bih0, bhh0, bih1, bhh1);
    lstm_main<<<B_TOT / TILE_B, NTH, smem_bytes>>>(x, Whh0, Wih1, Whh1, W_out, b_out, out);
}

// round 15
// speedup vs baseline: 1.0007x; 1.0007x over previous
#include <cuda_runtime.h>
#include <math.h>

// Problem constants
#define B_TOT  16384
#define T_LEN  128
#define F_DIM  9
#define H_DIM  128
#define O_DIM  12
#define G_DIM  512     // 4*H
#define TILE_B 64
#define NTH    512     // 16 warps: warp owns 8 rows x 256 cols (2 units x 4 gates per lane)
#define KC     16      // k-chunk staged per ping-pong step

typedef unsigned long long ull;

// ---------------- packed f32x2 helpers ----------------
__device__ __forceinline__ ull pk2(float x, float y) {
    ull r;
    asm("mov.b64 %0, {%1, %2};" : "=l"(r) : "f"(x), "f"(y));
    return r;
}
__device__ __forceinline__ void unpk2(ull v, float& lo, float& hi) {
    asm("mov.b64 {%0, %1}, %2;" : "=f"(lo), "=f"(hi) : "l"(v));
}
__device__ __forceinline__ ull fma2(ull a, ull b, ull c) {
    ull d;
    asm("fma.rn.f32x2 %0, %1, %2, %3;" : "=l"(d) : "l"(a), "l"(b), "l"(c));
    return d;
}

// ---------------- pointwise gate math ----------------
__device__ __forceinline__ float sigf(float x) {
    return __fdividef(1.0f, 1.0f + __expf(-x));
}
__device__ __forceinline__ float tanhfast(float x) {
    float xc = fminf(fmaxf(x, -15.0f), 15.0f);
    float e = __expf(2.0f * xc);
    return __fdividef(e - 1.0f, e + 1.0f);
}

// ---------------- staging permutation ----------------
// Column c (0..511) of a gate matrix decomposes as: g = c>>7 (gate), hf = (c>>6)&1,
// l = (c>>1)&31 (lane), u = c&1. Staged position within a 512-float k-row:
//   pos = (g>>1)*256 + hf*128 + l*4 + (g&1)*2 + u
// Reader (warp-half hf, lane l) then finds its 8 weights per k as TWO contiguous
// float4s at offsets  sel*256 + hf*128 + l*4 , sel = 0/1  -> LDS.128 as ulonglong2,
// each ull already the packed f32x2 (unit u0, u0+1) for one gate.
__device__ __forceinline__ int stage_pos(int c) {
    int g = c >> 7, hf = (c >> 6) & 1, l = (c >> 1) & 31, u = c & 1;
    return ((g >> 1) << 8) + (hf << 7) + (l << 2) + ((g & 1) << 1) + u;
}

// ---------------- precomputed folded weights ----------------
// WxP = (Wih0 @ W_in) stored PERMUTED: WxP[f*512 + stage_pos(c)]
// beff = Wih0 @ b_in + bih0 + bhh0 ; bias1 = bih1 + bhh1
__device__ float g_WxP[F_DIM * G_DIM];
__device__ float g_beff[G_DIM];
__device__ float g_bias1[G_DIM];

__global__ void precompute_kernel(const float* __restrict__ Wih0,
                                  const float* __restrict__ W_in,
                                  const float* __restrict__ b_in,
                                  const float* __restrict__ bih0,
                                  const float* __restrict__ bhh0,
                                  const float* __restrict__ bih1,
                                  const float* __restrict__ bhh1) {
    int j = threadIdx.x;  // 0..511 : column of the gate matrices
    float acc[F_DIM];
#pragma unroll
    for (int f = 0; f < F_DIM; f++) acc[f] = 0.0f;
    float bacc = 0.0f;
    for (int k = 0; k < H_DIM; k++) {
        float w = Wih0[j * H_DIM + k];
        bacc += w * b_in[k];
#pragma unroll
        for (int f = 0; f < F_DIM; f++) acc[f] += w * W_in[k * F_DIM + f];
    }
    int pos = stage_pos(j);
#pragma unroll
    for (int f = 0; f < F_DIM; f++) g_WxP[f * G_DIM + pos] = acc[f];
    g_beff[j] = bacc + bih0[j] + bhh0[j];
    g_bias1[j] = bih1[j] + bhh1[j];
}

// ---------------- helpers for the main kernel ----------------
__device__ __forceinline__ void init_acc(const float* __restrict__ sBias, int u0,
                                         ull (&acc)[4][8]) {
#pragma unroll
    for (int g = 0; g < 4; g++) {
        ull b = *(const ull*)(sBias + g * H_DIM + u0);
#pragma unroll
        for (int r = 0; r < 8; r++) acc[g][r] = b;
    }
}

// prefetch one KC=16 chunk of one weight matrix: thread owns column j
__device__ __forceinline__ void ldg_chunk(int m,
                                          const float* __restrict__ Whh0,
                                          const float* __restrict__ Wih1,
                                          const float* __restrict__ Whh1,
                                          int j, float4 (&ra)[4]) {
    const float* src = (m < 8) ? Whh0 : ((m < 16) ? Wih1 : Whh1);
    const float4* p = (const float4*)(src + (size_t)j * H_DIM + (m & 7) * KC);
#pragma unroll
    for (int i = 0; i < 4; i++) ra[i] = p[i];
}

// store chunk into staging buffer in permuted layout: buf[k*512 + pos]
__device__ __forceinline__ void sts_chunk(float* __restrict__ buf, int pos,
                                          const float4 (&ra)[4]) {
#pragma unroll
    for (int i = 0; i < 4; i++) {
        buf[(i * 4 + 0) * G_DIM + pos] = ra[i].x;
        buf[(i * 4 + 1) * G_DIM + pos] = ra[i].y;
        buf[(i * 4 + 2) * G_DIM + pos] = ra[i].z;
        buf[(i * 4 + 3) * G_DIM + pos] = ra[i].w;
    }
}

// Inner GEMM over a KC=16 chunk. Sp -> S[r0][k0] (row stride 128).
// base = hf*128 + lane*4 : this thread's slot within a staged k-row.
__device__ __forceinline__ void gemm16(const float* __restrict__ Sp,
                                       const float* __restrict__ buf,
                                       int base, ull (&acc)[4][8]) {
#pragma unroll
    for (int g2 = 0; g2 < 8; g2++) {          // groups of 2 k
        float2 h2[8];
#pragma unroll
        for (int r = 0; r < 8; r++)
            h2[r] = *(const float2*)(Sp + r * H_DIM + g2 * 2);
#pragma unroll
        for (int kk = 0; kk < 2; kk++) {
            const float* wp = buf + (g2 * 2 + kk) * G_DIM + base;
            ulonglong2 wa = *(const ulonglong2*)(wp);         // gates i,f (2 units each)
            ulonglong2 wb = *(const ulonglong2*)(wp + 256);   // gates g,o
#pragma unroll
            for (int r = 0; r < 8; r++) {
                float hv = kk ? h2[r].y : h2[r].x;
                ull hp = pk2(hv, hv);
                acc[0][r] = fma2(wa.x, hp, acc[0][r]);
                acc[1][r] = fma2(wa.y, hp, acc[1][r]);
                acc[2][r] = fma2(wb.x, hp, acc[2][r]);
                acc[3][r] = fma2(wb.y, hp, acc[3][r]);
            }
        }
    }
}

// x-part GEMM: K=9, permuted weights straight from global (L1/L2 resident, 18KB)
__device__ __forceinline__ void gemm_x(const float* __restrict__ Sp,  // sXs + r0*12
                                       int base, ull (&acc)[4][8]) {
#pragma unroll
    for (int k = 0; k < F_DIM; k++) {
        const float* wp = g_WxP + k * G_DIM + base;
        ulonglong2 wa = *(const ulonglong2*)(wp);
        ulonglong2 wb = *(const ulonglong2*)(wp + 256);
#pragma unroll
        for (int r = 0; r < 8; r++) {
            float hv = Sp[r * 12 + k];
            ull hp = pk2(hv, hv);
            acc[0][r] = fma2(wa.x, hp, acc[0][r]);
            acc[1][r] = fma2(wa.y, hp, acc[1][r]);
            acc[2][r] = fma2(wb.x, hp, acc[2][r]);
            acc[3][r] = fma2(wb.y, hp, acc[3][r]);
        }
    }
}

__device__ __forceinline__ void cell_update(ull (&acc)[4][8],
                                            float* __restrict__ sC,
                                            float* __restrict__ sH,
                                            int r0, int u0) {
#pragma unroll
    for (int r = 0; r < 8; r++) {
        float i0, i1, f0, f1, gg0, gg1, o0, o1;
        unpk2(acc[0][r], i0, i1);
        unpk2(acc[1][r], f0, f1);
        unpk2(acc[2][r], gg0, gg1);
        unpk2(acc[3][r], o0, o1);
        float* cp = sC + (r0 + r) * H_DIM + u0;
        float2 c2 = *(float2*)cp;
        float cn0 = sigf(f0) * c2.x + sigf(i0) * tanhfast(gg0);
        float cn1 = sigf(f1) * c2.y + sigf(i1) * tanhfast(gg1);
        float hn0 = sigf(o0) * tanhfast(cn0);
        float hn1 = sigf(o1) * tanhfast(cn1);
        *(float2*)cp = make_float2(cn0, cn1);
        *(float2*)(sH + (r0 + r) * H_DIM + u0) = make_float2(hn0, hn1);
    }
}

// ---------------- main persistent-tile LSTM kernel ----------------
// grid = 256 CTAs x 512 threads; each CTA owns 64 batch rows for all 128 steps.
// Warp (w): hf = w>>3 (column half), row group rg = w&7 -> rows rg*8..rg*8+7.
// Lane owns units u0 = hf*64 + lane*2 (+1) for all 4 gates. acc = 32 ull.
__global__ void __launch_bounds__(NTH, 1)
lstm_main(const float* __restrict__ x,
          const float* __restrict__ Whh0,
          const float* __restrict__ Wih1,
          const float* __restrict__ Whh1,
          const float* __restrict__ W_out,
          const float* __restrict__ b_out,
          float* __restrict__ out) {
    extern __shared__ float smem[];
    float* sXs    = smem;                  // 64*12  = 768
    float* sH0    = sXs + 768;             // 8192
    float* sH1    = sH0 + 8192;            // 8192
    float* sC0    = sH1 + 8192;            // 8192
    float* sC1    = sC0 + 8192;            // 8192
    float* sW     = sC1 + 8192;            // 2 x 8192 ping-pong (permuted chunks)
    float* sBeff  = sW + 16384;            // 512
    float* sBias1 = sBeff + 512;           // 512

    const int tid  = threadIdx.x;
    const int lane = tid & 31;
    const int warp = tid >> 5;
    const int hf   = warp >> 3;
    const int r0   = (warp & 7) * 8;        // 8 rows per warp
    const int u0   = hf * 64 + lane * 2;    // 2 units per gate per thread
    const int base = hf * 128 + lane * 4;   // slot within staged k-row
    const int b0   = blockIdx.x * TILE_B;
    const int spos = stage_pos(tid);        // where this thread's loaded column lands

    // init states + resident biases
    for (int i = tid; i < 4 * 8192; i += NTH) sH0[i] = 0.0f;   // H0,H1,C0,C1 contiguous
    for (int i = tid; i < G_DIM; i += NTH) { sBeff[i] = g_beff[i]; sBias1[i] = g_bias1[i]; }
    __syncthreads();

    float4 ra[4];
    ldg_chunk(0, Whh0, Wih1, Whh1, tid, ra);   // prefetch chunk 0

    for (int t = 0; t < T_LEN; t++) {
        // x tile for this timestep
        for (int i = tid; i < TILE_B * F_DIM; i += NTH) {
            int r = i / F_DIM, f = i - r * F_DIM;
            sXs[r * 12 + f] = x[(size_t)(b0 + r) * (T_LEN * F_DIM) + t * F_DIM + f];
        }
        __syncthreads();

        // ---- layer 0 ----
        ull acc[4][8];
        init_acc(sBeff, u0, acc);
        gemm_x(&sXs[r0 * 12], base, acc);               // folded x-part, K=9
#pragma unroll 1
        for (int m = 0; m < 8; m++) {                   // Whh0, K=128
            float* buf = sW + (m & 1) * 8192;
            sts_chunk(buf, spos, ra);
            ldg_chunk(m + 1, Whh0, Wih1, Whh1, tid, ra);
            __syncthreads();
            gemm16(&sH0[r0 * H_DIM + m * KC], buf, base, acc);
        }
        __syncthreads();
        cell_update(acc, sC0, sH0, r0, u0);
        __syncthreads();

        // ---- layer 1 ----
        init_acc(sBias1, u0, acc);
#pragma unroll 1
        for (int m = 8; m < 24; m++) {                  // Wih1 (h0-new) then Whh1 (h1-old)
            float* buf = sW + (m & 1) * 8192;
            sts_chunk(buf, spos, ra);
            int mn = (m + 1 == 24) ? 0 : (m + 1);
            ldg_chunk(mn, Whh0, Wih1, Whh1, tid, ra);
            __syncthreads();
            const float* S = (m < 16) ? sH0 : sH1;
            gemm16(&S[r0 * H_DIM + (m & 7) * KC], buf, base, acc);
        }
        __syncthreads();
        cell_update(acc, sC1, sH1, r0, u0);
        __syncthreads();
    }

    // ---- epilogue: logits + softmax on last h1 ----
    if (tid < TILE_B) {
        int r = tid;
        const float* hr = &sH1[r * H_DIM];
        float lg[O_DIM];
#pragma unroll
        for (int o = 0; o < O_DIM; o++) {
            float s = b_out[o];
            for (int k = 0; k < H_DIM; k++) s += hr[k] * W_out[o * H_DIM + k];
            lg[o] = s;
        }
        float m = lg[0];
#pragma unroll
        for (int o = 1; o < O_DIM; o++) m = fmaxf(m, lg[o]);
        float sum = 0.0f;
#pragma unroll
        for (int o = 0; o < O_DIM; o++) { lg[o] = __expf(lg[o] - m); sum += lg[o]; }
        float inv = __fdividef(1.0f, sum);
#pragma unroll
        for (int o = 0; o < O_DIM; o++) out[(size_t)(b0 + r) * O_DIM + o] = lg[o] * inv;
    }
}

// ---------------- launch ----------------
extern "C" void kernel_launch(void* const* d_in, const int* in_sizes, int n_in,
                              void* d_out, int out_size) {
    (void)in_sizes; (void)n_in; (void)out_size;
    const float* x     = (const float*)d_in[0];
    const float* W_in  = (const float*)d_in[1];
    const float* b_in  = (const float*)d_in[2];
    const float* Wih0  = (const float*)d_in[3];
    const float* Whh0  = (const float*)d_in[4];
    const float* bih0  = (const float*)d_in[5];
    const float* bhh0  = (const float*)d_in[6];
    const float* Wih1  = (const float*)d_in[7];
    const float* Whh1  = (const float*)d_in[8];
    const float* bih1  = (const float*)d_in[9];
    const float* bhh1  = (const float*)d_in[10];
    const float* W_out = (const float*)d_in[11];
    const float* b_out = (const float*)d_in[12];
    float* out = (float*)d_out;

    const size_t smem_bytes = (size_t)(768 + 8192 * 6 + 1024) * sizeof(float); // 203776
    cudaFuncSetAttribute(lstm_main, cudaFuncAttributeMaxDynamicSharedMemorySize, (int)smem_bytes);

    precompute_kernel<<<1, G_DIM>>>(Wih0, W_in, b_in, bih0, bhh0, bih1, bhh1);
    lstm_main<<<B_TOT / TILE_B, NTH, smem_bytes>>>(x, Whh0, Wih1, Whh1, W_out, b_out, out);
}

// round 17
// speedup vs baseline: 6.6938x; 6.6892x over previous
#include <cuda_runtime.h>
#include <cuda_fp16.h>
#include <stdint.h>
#include <math.h>

#define NTH 512

// ---------------- packed weight fragments (fp16, mma B-fragment order) ----------------
// ksg 0: Bx (folded x-proj, K=16, cols 9..15 zero); 1-8: Whh0; 9-16: Wih1; 17-24: Whh1.
// index = (ksg*64 + n_tile)*32 + lane ; each uint2 = {W[n][k0],W[n][k0+1],W[n][k0+8],W[n][k0+9]}
// with n = n_tile*8 + lane/4, k0 = (lane%4)*2.  Gate cols unit-major: n <-> weight row (n%4)*128 + n/4.
__device__ uint2 g_packs[25 * 64 * 32];
__device__ float g_beff[512];    // Wih0@b_in + bih0 + bhh0, unit-major order
__device__ float g_bias1[512];   // bih1 + bhh1, unit-major order

__global__ void precompute_kernel(const float* __restrict__ Wih0, const float* __restrict__ W_in,
                                  const float* __restrict__ b_in, const float* __restrict__ bih0,
                                  const float* __restrict__ bhh0, const float* __restrict__ bih1,
                                  const float* __restrict__ bhh1, const float* __restrict__ Whh0,
                                  const float* __restrict__ Wih1, const float* __restrict__ Whh1) {
    __shared__ float sWeff[512 * 9];
    int n = threadIdx.x;                 // unit-major gate column
    int wr = (n & 3) * 128 + (n >> 2);   // original weight row: gate*128 + unit
    float f[9];
#pragma unroll
    for (int j = 0; j < 9; j++) f[j] = 0.f;
    float bacc = 0.f;
    for (int k = 0; k < 128; k++) {
        float w = Wih0[wr * 128 + k];
        bacc += w * b_in[k];
#pragma unroll
        for (int j = 0; j < 9; j++) f[j] += w * W_in[k * 9 + j];
    }
#pragma unroll
    for (int j = 0; j < 9; j++) sWeff[n * 9 + j] = f[j];
    g_beff[n] = bacc + bih0[wr] + bhh0[wr];
    g_bias1[n] = bih1[wr] + bhh1[wr];
    __syncthreads();

    for (int idx = threadIdx.x; idx < 25 * 64 * 32; idx += NTH) {
        int lane = idx & 31, rest = idx >> 5, nt = rest & 63, ksg = rest >> 6;
        int nn = nt * 8 + (lane >> 2), k0 = (lane & 3) * 2;
        int wrr = (nn & 3) * 128 + (nn >> 2);
        float v0, v1, v2, v3;
        if (ksg == 0) {
            v0 = (k0 < 9) ? sWeff[nn * 9 + k0] : 0.f;
            v1 = (k0 + 1 < 9) ? sWeff[nn * 9 + k0 + 1] : 0.f;
            v2 = (k0 + 8 < 9) ? sWeff[nn * 9 + k0 + 8] : 0.f;
            v3 = 0.f;
        } else {
            const float* W = (ksg <= 8) ? Whh0 : ((ksg <= 16) ? Wih1 : Whh1);
            const float* p = W + (size_t)wrr * 128 + ((ksg - 1) & 7) * 16;
            v0 = p[k0]; v1 = p[k0 + 1]; v2 = p[k0 + 8]; v3 = p[k0 + 9];
        }
        __half2 ha = __floats2half2_rn(v0, v1), hb = __floats2half2_rn(v2, v3);
        uint2 u;
        u.x = *(uint32_t*)&ha; u.y = *(uint32_t*)&hb;
        g_packs[idx] = u;
    }
}

// ---------------- SMEM layout (bytes) ----------------
#define OFF_AX   0u        // A_x  [128 x 16] fp16, 32B rows, 1-bit chunk swizzle    4KB
#define OFF_AH0  4096u     // h0   [128 x 128] fp16, 256B rows, chunk^(r&7) swizzle  32KB
#define OFF_AH1  36864u    // h1                                                     32KB
#define OFF_C0   69632u    // c0 [128][130] f32                                      66560B
#define OFF_C1   136192u   // c1                                                     66560B
#define OFF_BE   202752u   // beff  f32[512]
#define OFF_B1   204800u   // bias1 f32[512]
#define SMEM_SZ  206848u

__device__ __forceinline__ float sigf(float x) { return __fdividef(1.f, 1.f + __expf(-x)); }
__device__ __forceinline__ float tanh_(float x) {
    float c = fminf(fmaxf(x, -15.f), 15.f);
    float e = __expf(2.f * c);
    return __fdividef(e - 1.f, e + 1.f);
}
__device__ __forceinline__ uint32_t s32(const void* p) {
    uint32_t a;
    asm("{ .reg .u64 t; cvta.to.shared.u64 t, %1; cvt.u32.u64 %0, t; }" : "=r"(a) : "l"(p));
    return a;
}
__device__ __forceinline__ void ldsm4(uint32_t* a, uint32_t addr) {
    asm volatile("ldmatrix.sync.aligned.m8n8.x4.shared.b16 {%0,%1,%2,%3},[%4];"
                 : "=r"(a[0]), "=r"(a[1]), "=r"(a[2]), "=r"(a[3]) : "r"(addr));
}
__device__ __forceinline__ void mma_(float* d, const uint32_t* a, uint2 b) {
    asm volatile("mma.sync.aligned.m16n8k16.row.col.f32.f16.f16.f32 "
                 "{%0,%1,%2,%3},{%4,%5,%6,%7},{%8,%9},{%0,%1,%2,%3};"
                 : "+f"(d[0]), "+f"(d[1]), "+f"(d[2]), "+f"(d[3])
                 : "r"(a[0]), "r"(a[1]), "r"(a[2]), "r"(a[3]), "r"(b.x), "r"(b.y));
}

// warp w: wm = w&3 -> rows wm*32..+31 (2 m16 tiles); wn = w>>2 -> cols wn*128..+127 (16 n8 tiles).
// 4 N-blocks of 4 tiles: acc = 2x4x4 = 32 f32. Cell update: shfl.xor(1) completes i/f/g/o per unit.
__global__ void __launch_bounds__(NTH, 1)
lstm_hmma(const float* __restrict__ x, const float* __restrict__ W_out,
          const float* __restrict__ b_out, float* __restrict__ out) {
    extern __shared__ char smem[];
    const uint32_t sb = s32(smem);
    const int tid = threadIdx.x, lane = tid & 31, w = tid >> 5;
    const int wm = w & 3, wn = w >> 2;
    const int lq = lane & 3, odd = lq & 1, uh = lq >> 1, g8 = lane >> 2;
    const int b0 = blockIdx.x * 128;

    // zero h0/h1/c0/c1/A_x ; stage biases
    for (int i = tid; i < (int)(OFF_BE / 4); i += NTH) ((float*)smem)[i] = 0.f;
    float* sBE = (float*)(smem + OFF_BE);
    float* sB1 = (float*)(smem + OFF_B1);
    for (int i = tid; i < 512; i += NTH) { sBE[i] = g_beff[i]; sB1[i] = g_bias1[i]; }
    __syncthreads();

    // ldmatrix lane geometry: lanes 0-7 rows 0-7 k0; 8-15 rows 8-15 k0; 16-23 rows 0-7 k0+8; 24-31 rows 8-15 k0+8
    const int seg = lane >> 3, rr8 = (seg & 1) * 8 + (lane & 7), kad = (seg >> 1) * 8;
    const int rA0 = wm * 32 + rr8, rA1 = wm * 32 + 16 + rr8;
    const int l7 = lane & 7;  // == rA&7 (rows offset by multiples of 8)
    const uint32_t axA0 = sb + OFF_AX + rA0 * 32 + ((((kad >> 3)) ^ (rA0 & 1)) << 4);
    const uint32_t axA1 = sb + OFF_AX + rA1 * 32 + ((((kad >> 3)) ^ (rA1 & 1)) << 4);

    float* c0p = (float*)(smem + OFF_C0);
    float* c1p = (float*)(smem + OFF_C1);
    unsigned short hst[32];

    for (int t = 0; t < 128; t++) {
        // ---- A_x fill: x[b][t][0..8] fp32 -> fp16 (cols 9..15 stay zero) ----
        if (tid < 128) {
            const float* xp = x + (size_t)(b0 + tid) * (128 * 9) + t * 9;
#pragma unroll
            for (int k = 0; k < 9; k++)
                *(unsigned short*)(smem + OFF_AX + tid * 32 + (((k >> 3) ^ (tid & 1)) << 4) + (k & 7) * 2)
                    = __half_as_ushort(__float2half(xp[k]));
        }
        __syncthreads();

        // ---------------- layer 0: D = beff + A_x*Bx + h0*Whh0 ----------------
#pragma unroll 1
        for (int nb = 0; nb < 4; nb++) {
            const int ntb = wn * 16 + nb * 4;
            float acc[2][4][4];
#pragma unroll
            for (int ti = 0; ti < 4; ti++) {
                int n0 = (ntb + ti) * 8 + lq * 2;
                float v0 = sBE[n0], v1 = sBE[n0 + 1];
                acc[0][ti][0] = v0; acc[0][ti][1] = v1; acc[0][ti][2] = v0; acc[0][ti][3] = v1;
                acc[1][ti][0] = v0; acc[1][ti][1] = v1; acc[1][ti][2] = v0; acc[1][ti][3] = v1;
            }
            const uint2* pB = g_packs + ntb * 32 + lane;
            uint2 Bc[4];
#pragma unroll
            for (int ti = 0; ti < 4; ti++) Bc[ti] = pB[ti * 32];
#pragma unroll
            for (int ks = 0; ks < 9; ks++) {
                uint2 Bn[4];
                if (ks < 8) {
                    const uint2* pn = pB + (ks + 1) * 2048;
#pragma unroll
                    for (int ti = 0; ti < 4; ti++) Bn[ti] = pn[ti * 32];
                }
                uint32_t a0[4], a1[4];
                if (ks == 0) { ldsm4(a0, axA0); ldsm4(a1, axA1); }
                else {
                    int ch = (((ks - 1) * 16 + kad) >> 3) ^ l7;
                    ldsm4(a0, sb + OFF_AH0 + rA0 * 256 + ch * 16);
                    ldsm4(a1, sb + OFF_AH0 + rA1 * 256 + ch * 16);
                }
#pragma unroll
                for (int ti = 0; ti < 4; ti++) { mma_(acc[0][ti], a0, Bc[ti]); mma_(acc[1][ti], a1, Bc[ti]); }
                if (ks < 8) {
#pragma unroll
                    for (int ti = 0; ti < 4; ti++) Bc[ti] = Bn[ti];
                }
            }
            // cell update (gate cols unit-major: lq pair {i,f}/{g,o} -> shfl.xor(1))
#pragma unroll
            for (int mt = 0; mt < 2; mt++)
#pragma unroll
                for (int ti = 0; ti < 4; ti++) {
                    float A0 = acc[mt][ti][0], A1 = acc[mt][ti][1], A2 = acc[mt][ti][2], A3 = acc[mt][ti][3];
                    float s1 = __shfl_xor_sync(0xffffffffu, odd ? A0 : A2, 1);
                    float s2 = __shfl_xor_sync(0xffffffffu, odd ? A1 : A3, 1);
                    float gi = odd ? s1 : A0, gf = odd ? s2 : A1, gg = odd ? A2 : s1, go = odd ? A3 : s2;
                    int r = wm * 32 + mt * 16 + g8 + (odd << 3);
                    int U = (ntb + ti) * 2 + uh;
                    float* cp = c0p + r * 130 + U;
                    float cn = sigf(gf) * cp[0] + sigf(gi) * tanh_(gg);
                    cp[0] = cn;
                    hst[nb * 8 + mt * 4 + ti] = __half_as_ushort(__float2half(sigf(go) * tanh_(cn)));
                }
        }
        __syncthreads();   // all reads of old h0 done
#pragma unroll 1
        for (int nb = 0; nb < 4; nb++)
#pragma unroll
            for (int mt = 0; mt < 2; mt++)
#pragma unroll
                for (int ti = 0; ti < 4; ti++) {
                    int r = wm * 32 + mt * 16 + g8 + (odd << 3);
                    int U = (wn * 16 + nb * 4 + ti) * 2 + uh;
                    *(unsigned short*)(smem + OFF_AH0 + r * 256 + (((U >> 3) ^ (r & 7)) << 4) + (U & 7) * 2)
                        = hst[nb * 8 + mt * 4 + ti];
                }
        __syncthreads();   // new h0 visible

        // ---------------- layer 1: D = bias1 + h0new*Wih1 + h1old*Whh1 ----------------
#pragma unroll 1
        for (int nb = 0; nb < 4; nb++) {
            const int ntb = wn * 16 + nb * 4;
            float acc[2][4][4];
#pragma unroll
            for (int ti = 0; ti < 4; ti++) {
                int n0 = (ntb + ti) * 8 + lq * 2;
                float v0 = sB1[n0], v1 = sB1[n0 + 1];
                acc[0][ti][0] = v0; acc[0][ti][1] = v1; acc[0][ti][2] = v0; acc[0][ti][3] = v1;
                acc[1][ti][0] = v0; acc[1][ti][1] = v1; acc[1][ti][2] = v0; acc[1][ti][3] = v1;
            }
            const uint2* pB = g_packs + 9 * 2048 + ntb * 32 + lane;
            uint2 Bc[4];
#pragma unroll
            for (int ti = 0; ti < 4; ti++) Bc[ti] = pB[ti * 32];
#pragma unroll
            for (int ks = 0; ks < 16; ks++) {
                uint2 Bn[4];
                if (ks < 15) {
                    const uint2* pn = pB + (ks + 1) * 2048;
#pragma unroll
                    for (int ti = 0; ti < 4; ti++) Bn[ti] = pn[ti * 32];
                }
                uint32_t a0[4], a1[4];
                uint32_t ab = (ks < 8) ? (sb + OFF_AH0) : (sb + OFF_AH1);
                int ch = (((ks & 7) * 16 + kad) >> 3) ^ l7;
                ldsm4(a0, ab + rA0 * 256 + ch * 16);
                ldsm4(a1, ab + rA1 * 256 + ch * 16);
#pragma unroll
                for (int ti = 0; ti < 4; ti++) { mma_(acc[0][ti], a0, Bc[ti]); mma_(acc[1][ti], a1, Bc[ti]); }
                if (ks < 15) {
#pragma unroll
                    for (int ti = 0; ti < 4; ti++) Bc[ti] = Bn[ti];
                }
            }
#pragma unroll
            for (int mt = 0; mt < 2; mt++)
#pragma unroll
                for (int ti = 0; ti < 4; ti++) {
                    float A0 = acc[mt][ti][0], A1 = acc[mt][ti][1], A2 = acc[mt][ti][2], A3 = acc[mt][ti][3];
                    float s1 = __shfl_xor_sync(0xffffffffu, odd ? A0 : A2, 1);
                    float s2 = __shfl_xor_sync(0xffffffffu, odd ? A1 : A3, 1);
                    float gi = odd ? s1 : A0, gf = odd ? s2 : A1, gg = odd ? A2 : s1, go = odd ? A3 : s2;
                    int r = wm * 32 + mt * 16 + g8 + (odd << 3);
                    int U = (ntb + ti) * 2 + uh;
                    float* cp = c1p + r * 130 + U;
                    float cn = sigf(gf) * cp[0] + sigf(gi) * tanh_(gg);
                    cp[0] = cn;
                    hst[nb * 8 + mt * 4 + ti] = __half_as_ushort(__float2half(sigf(go) * tanh_(cn)));
                }
        }
        __syncthreads();
#pragma unroll 1
        for (int nb = 0; nb < 4; nb++)
#pragma unroll
            for (int mt = 0; mt < 2; mt++)
#pragma unroll
                for (int ti = 0; ti < 4; ti++) {
                    int r = wm * 32 + mt * 16 + g8 + (odd << 3);
                    int U = (wn * 16 + nb * 4 + ti) * 2 + uh;
                    *(unsigned short*)(smem + OFF_AH1 + r * 256 + (((U >> 3) ^ (r & 7)) << 4) + (U & 7) * 2)
                        = hst[nb * 8 + mt * 4 + ti];
                }
        __syncthreads();
    }

    // ---------------- epilogue: logits + softmax on final h1 ----------------
    if (tid < 128) {
        float lg[12];
#pragma unroll
        for (int o = 0; o < 12; o++) lg[o] = b_out[o];
        for (int k = 0; k < 128; k++) {
            float hv = __half2float(__ushort_as_half(
                *(unsigned short*)(smem + OFF_AH1 + tid * 256 + (((k >> 3) ^ (tid & 7)) << 4) + (k & 7) * 2)));
#pragma unroll
            for (int o = 0; o < 12; o++) lg[o] += hv * W_out[o * 128 + k];
        }
        float m = lg[0];
#pragma unroll
        for (int o = 1; o < 12; o++) m = fmaxf(m, lg[o]);
        float s = 0.f;
#pragma unroll
        for (int o = 0; o < 12; o++) { lg[o] = __expf(lg[o] - m); s += lg[o]; }
        float inv = __fdividef(1.f, s);
#pragma unroll
        for (int o = 0; o < 12; o++) out[(size_t)(b0 + tid) * 12 + o] = lg[o] * inv;
    }
}

// ---------------- launch ----------------
extern "C" void kernel_launch(void* const* d_in, const int* in_sizes, int n_in,
                              void* d_out, int out_size) {
    (void)in_sizes; (void)n_in; (void)out_size;
    const float* x     = (const float*)d_in[0];
    const float* W_in  = (const float*)d_in[1];
    const float* b_in  = (const float*)d_in[2];
    const float* Wih0  = (const float*)d_in[3];
    const float* Whh0  = (const float*)d_in[4];
    const float* bih0  = (const float*)d_in[5];
    const float* bhh0  = (const float*)d_in[6];
    const float* Wih1  = (const float*)d_in[7];
    const float* Whh1  = (const float*)d_in[8];
    const float* bih1  = (const float*)d_in[9];
    const float* bhh1  = (const float*)d_in[10];
    const float* W_out = (const float*)d_in[11];
    const float* b_out = (const float*)d_in[12];
    float* out = (float*)d_out;

    cudaFuncSetAttribute(lstm_hmma, cudaFuncAttributeMaxDynamicSharedMemorySize, (int)SMEM_SZ);

    precompute_kernel<<<1, NTH>>>(Wih0, W_in, b_in, bih0, bhh0, bih1, bhh1, Whh0, Wih1, Whh1);
    lstm_hmma<<<128, NTH, SMEM_SZ>>>(x, W_out, b_out, out);
}